// round 12
// baseline (speedup 1.0000x reference)
#include <cuda_runtime.h>
#include <cstdint>

#define B_ 128
#define T_ 64
#define D_ 256
#define H_ 256
#define NT 512
#define NPAIR 64
#define HH (H_ * H_)
#define BARP 1
#define BARA 2

// R8 base (all 512 threads GEMM, layer-pipelined producer/consumer CTAs)
// + rotating reducer group (stage_idx & 3) + asymmetric named barriers
// (non-reducers arrive PART without waiting, preload next stage's weight
// rows 8-15 + slack jobs during the reduce) + MUFU-based activations.

__device__ float g_h0buf[NPAIR][T_][2][H_];
__device__ int   g_flags[NPAIR * 32];

__device__ __forceinline__ void bar_arrive_(int id, int cnt) {
    asm volatile("bar.arrive %0, %1;" :: "r"(id), "r"(cnt) : "memory");
}
__device__ __forceinline__ void bar_sync_(int id, int cnt) {
    asm volatile("bar.sync %0, %1;" :: "r"(id), "r"(cnt) : "memory");
}
__device__ __forceinline__ float tanh_(float x) {
    return __fdividef(2.f, 1.f + __expf(-2.f * x)) - 1.f;
}
__device__ __forceinline__ float sigm_(float x) {
    return __fdividef(1.f, 1.f + __expf(-x));
}
__device__ __forceinline__ void f4fma(float4& a, float s, const float4 w) {
    a.x = fmaf(s, w.x, a.x); a.y = fmaf(s, w.y, a.y);
    a.z = fmaf(s, w.z, a.z); a.w = fmaf(s, w.w, a.w);
}
__device__ __forceinline__ float4 f4add(float4 a, float4 b) {
    return make_float4(a.x + b.x, a.y + b.y, a.z + b.z, a.w + b.w);
}
__device__ __forceinline__ void ld_grp(float4 (&w)[4], const float4* __restrict__ Wq, int g) {
    #pragma unroll
    for (int k = 0; k < 4; ++k) w[k] = Wq[g * 256 + k * 64];
}
__device__ __forceinline__ void fma_grp(const float4 (&w)[4], const float4 A0,
                                        const float4 A1, float4& c0, float4& c1) {
    f4fma(c0, A0.x, w[0]); f4fma(c1, A1.x, w[0]);
    f4fma(c0, A0.y, w[1]); f4fma(c1, A1.y, w[1]);
    f4fma(c0, A0.z, w[2]); f4fma(c1, A1.z, w[2]);
    f4fma(c0, A0.w, w[3]); f4fma(c1, A1.w, w[3]);
}

// matrix pass, rows 0-15 already in wp/w1/wa/wb; prefetch Wn rows 0-7
__device__ __forceinline__ void matpass_nopre(
    const float4* __restrict__ W, const float4* __restrict__ Wn,
    const float4* __restrict__ a0, const float4* __restrict__ a1,
    float4 (&wp)[4], float4 (&w1)[4], float4 (&wa)[4], float4 (&wb)[4],
    float4& c0, float4& c1)
{
    fma_grp(wp, a0[0], a1[0], c0, c1); ld_grp(wp, Wn, 0);
    fma_grp(w1, a0[1], a1[1], c0, c1); ld_grp(w1, Wn, 1);
    fma_grp(wa, a0[2], a1[2], c0, c1); ld_grp(wa, W, 4);
    fma_grp(wb, a0[3], a1[3], c0, c1); ld_grp(wb, W, 5);
    fma_grp(wa, a0[4], a1[4], c0, c1); ld_grp(wa, W, 6);
    fma_grp(wb, a0[5], a1[5], c0, c1); ld_grp(wb, W, 7);
    fma_grp(wa, a0[6], a1[6], c0, c1);
    fma_grp(wb, a0[7], a1[7], c0, c1);
}
// matrix pass, only rows 0-7 in wp/w1 (rows 8-15 loaded inline)
__device__ __forceinline__ void matpass_inline(
    const float4* __restrict__ W, const float4* __restrict__ Wn,
    const float4* __restrict__ a0, const float4* __restrict__ a1,
    float4 (&wp)[4], float4 (&w1)[4], float4 (&wa)[4], float4 (&wb)[4],
    float4& c0, float4& c1)
{
    ld_grp(wa, W, 2); ld_grp(wb, W, 3);
    fma_grp(wp, a0[0], a1[0], c0, c1); ld_grp(wp, Wn, 0);
    fma_grp(w1, a0[1], a1[1], c0, c1); ld_grp(w1, Wn, 1);
    fma_grp(wa, a0[2], a1[2], c0, c1); ld_grp(wa, W, 4);
    fma_grp(wb, a0[3], a1[3], c0, c1); ld_grp(wb, W, 5);
    fma_grp(wa, a0[4], a1[4], c0, c1); ld_grp(wa, W, 6);
    fma_grp(wb, a0[5], a1[5], c0, c1); ld_grp(wb, W, 7);
    fma_grp(wa, a0[6], a1[6], c0, c1);
    fma_grp(wb, a0[7], a1[7], c0, c1);
}

__device__ __forceinline__ float4 reduce8(const float4 (&p)[8][2][64], int row, int q) {
    float4 s  = f4add(p[0][row][q], p[1][row][q]);
    float4 s2 = f4add(p[2][row][q], p[3][row][q]);
    float4 s3 = f4add(p[4][row][q], p[5][row][q]);
    float4 s4 = f4add(p[6][row][q], p[7][row][q]);
    return f4add(f4add(s, s2), f4add(s3, s4));
}

__global__ void reset_flags_kernel() {
    g_flags[threadIdx.x * 32] = 0;
}

__global__ void __launch_bounds__(NT, 1)
rnn_rot_kernel(const float* __restrict__ x,       // [B,T,D]
               const float* __restrict__ hidden,  // [L,B,H]
               const float* __restrict__ Win0,    // [T,D,H]
               const float* __restrict__ Wh0,     // [T,3,H,H]
               const float* __restrict__ b0in,    // [T,3,H]
               const float* __restrict__ Win1,    // [T,H,H]
               const float* __restrict__ Wh1,     // [T,3,H,H]
               const float* __restrict__ b1in,    // [T,3,H]
               float* __restrict__ out,           // [B,T,H]
               float* __restrict__ hout)          // [L,B,H]
{
    __shared__ __align__(16) float xs[2][H_];
    __shared__ __align__(16) float hs[2][H_];
    __shared__ __align__(16) float n0s[2][H_];
    __shared__ __align__(16) float n1s[2][H_];
    __shared__ __align__(16) float bs[2][3][H_];
    __shared__ __align__(16) float4 part[8][2][64];

    const int tid = threadIdx.x;
    const int q = tid & 63;
    const int kc = tid >> 6;
    const int grp = tid >> 7;          // rotation group 0..3
    const int l = tid & 127;           // index within group
    const int rrow = l >> 6, rq = l & 63;
    const int pair = blockIdx.x >> 1;
    const int layer = blockIdx.x & 1;
    const int r0 = pair * 2;

    const float* Wi_base   = layer ? Win1 : Win0;
    const float* Wh_base   = layer ? Wh1 : Wh0;
    const float* bias_base = layer ? b1in : b0in;

    {
        int row = tid >> 8, j = tid & 255;
        hs[row][j] = hidden[((size_t)layer * B_ + r0 + row) * H_ + j];
        if (layer == 0)
            xs[row][j] = x[((size_t)(r0 + row) * T_) * D_ + j];
    }
    if (tid < 192)
        *reinterpret_cast<float4*>(&bs[0][0][0] + tid * 4) =
            *reinterpret_cast<const float4*>(bias_base + tid * 4);
    if (layer == 1 && tid == 0) {
        int v;
        do {
            asm volatile("ld.acquire.gpu.global.s32 %0, [%1];"
                         : "=r"(v) : "l"(&g_flags[pair * 32]) : "memory");
            if (v < 1) __nanosleep(64);
        } while (v < 1);
    }
    __syncthreads();

    const int woff = kc * 32 * 64 + q;           // float4 units
    const float4* hs0 = reinterpret_cast<const float4*>(hs[0]) + kc * 8;
    const float4* hs1 = reinterpret_cast<const float4*>(hs[1]) + kc * 8;
    const float4* xs0 = reinterpret_cast<const float4*>(xs[0]) + kc * 8;
    const float4* xs1 = reinterpret_cast<const float4*>(xs[1]) + kc * 8;
    const float4* n00 = reinterpret_cast<const float4*>(n0s[0]) + kc * 8;
    const float4* n01 = reinterpret_cast<const float4*>(n0s[1]) + kc * 8;
    const float4* n10 = reinterpret_cast<const float4*>(n1s[0]) + kc * 8;
    const float4* n11 = reinterpret_cast<const float4*>(n1s[1]) + kc * 8;

    float4 wp[4], w1[4], wa[4], wb[4];
    {   // bootstrap: Wi(t=0) rows 0-15
        const float4* W = reinterpret_cast<const float4*>(Wi_base) + woff;
        ld_grp(wp, W, 0); ld_grp(w1, W, 1); ld_grp(wa, W, 2); ld_grp(wb, W, 3);
    }

    for (int t = 0; t < T_; ++t) {
        const float4* WqWi = reinterpret_cast<const float4*>(
            Wi_base + (size_t)t * (D_ * H_)) + woff;
        const float* WhT = Wh_base + (size_t)t * 3 * HH;
        const float4* WqWh0 = reinterpret_cast<const float4*>(WhT) + woff;
        const float4* WqWh1 = reinterpret_cast<const float4*>(WhT + HH) + woff;
        const float4* WqWh2 = reinterpret_cast<const float4*>(WhT + 2 * HH) + woff;
        const int tn = (t + 1 < T_) ? t + 1 : 0;
        const float4* WqWiN = reinterpret_cast<const float4*>(
            Wi_base + (size_t)tn * (D_ * H_)) + woff;
        const float* bsc = &bs[t & 1][0][0];
        const float4* bnext =
            reinterpret_cast<const float4*>(bias_base + (size_t)tn * 3 * H_);
        const int g3 = 3 * t;
        const int rg0 = g3 & 3, rg1 = (g3 + 1) & 3, rg2 = (g3 + 2) & 3;

        const float4* i0;
        const float4* i1;
        if (layer == 0) { i0 = xs0; i1 = xs1; }
        else {
            i0 = reinterpret_cast<const float4*>(&g_h0buf[pair][t][0][0]) + kc * 8;
            i1 = reinterpret_cast<const float4*>(&g_h0buf[pair][t][1][0]) + kc * 8;
        }

        // ================= stage A: in@Wi + h@Wh0 =================
        float4 acc0 = {0.f,0.f,0.f,0.f}, acc1 = {0.f,0.f,0.f,0.f};
        matpass_nopre(WqWi, WqWh0, i0, i1, wp, w1, wa, wb, acc0, acc1);
        matpass_inline(WqWh0, WqWh1, hs0, hs1, wp, w1, wa, wb, acc0, acc1);
        part[kc][0][q] = acc0; part[kc][1][q] = acc1;
        if (grp == rg0) {
            bar_sync_(BARP, NT);
            float4 s = reduce8(part, rrow, rq);
            float4 bv = *reinterpret_cast<const float4*>(bsc + 4 * rq);
            float4 v0 = make_float4(tanh_(s.x + bv.x), tanh_(s.y + bv.y),
                                    tanh_(s.z + bv.z), tanh_(s.w + bv.w));
            *reinterpret_cast<float4*>(&n0s[rrow][4 * rq]) = v0;
        } else {
            bar_arrive_(BARP, NT);
            if (grp == ((rg0 + 1) & 3))      // bias(t+1) first 128 float4
                reinterpret_cast<float4*>(&bs[(t + 1) & 1][0][0])[l] = bnext[l];
        }
        ld_grp(wa, WqWh1, 2); ld_grp(wb, WqWh1, 3);
        bar_sync_(BARA, NT);

        // ================= stage B: n0@Wh1 =================
        acc0 = make_float4(0.f,0.f,0.f,0.f); acc1 = acc0;
        matpass_nopre(WqWh1, WqWh2, n00, n01, wp, w1, wa, wb, acc0, acc1);
        part[kc][0][q] = acc0; part[kc][1][q] = acc1;
        if (grp == rg1) {
            bar_sync_(BARP, NT);
            float4 s = reduce8(part, rrow, rq);
            float4 bv = *reinterpret_cast<const float4*>(bsc + H_ + 4 * rq);
            float4 v0 = *reinterpret_cast<const float4*>(&n0s[rrow][4 * rq]);
            float4 u = make_float4(fmaxf(s.x + bv.x, 0.f) + v0.x,
                                   fmaxf(s.y + bv.y, 0.f) + v0.y,
                                   fmaxf(s.z + bv.z, 0.f) + v0.z,
                                   fmaxf(s.w + bv.w, 0.f) + v0.w);
            *reinterpret_cast<float4*>(&n1s[rrow][4 * rq]) = u;
        } else {
            bar_arrive_(BARP, NT);
            if (grp == ((rg1 + 1) & 3) && l < 64)   // bias(t+1) last 64 float4
                reinterpret_cast<float4*>(&bs[(t + 1) & 1][0][0])[128 + l] =
                    bnext[128 + l];
            if (grp == ((rg1 + 2) & 3) && layer == 0 && t + 1 < T_) {
                int rr = l >> 6, col = (l & 63) * 4;   // x(t+1) prefetch
                *reinterpret_cast<float4*>(&xs[rr][col]) =
                    *reinterpret_cast<const float4*>(
                        &x[((size_t)(r0 + rr) * T_ + t + 1) * D_ + col]);
            }
        }
        ld_grp(wa, WqWh2, 2); ld_grp(wb, WqWh2, 3);
        bar_sync_(BARA, NT);

        // ================= stage C: n1@Wh2 =================
        acc0 = make_float4(0.f,0.f,0.f,0.f); acc1 = acc0;
        matpass_nopre(WqWh2, WqWiN, n10, n11, wp, w1, wa, wb, acc0, acc1);
        part[kc][0][q] = acc0; part[kc][1][q] = acc1;
        if (grp == rg2) {
            bar_sync_(BARP, NT);
            float4 s = reduce8(part, rrow, rq);
            float4 bv = *reinterpret_cast<const float4*>(bsc + 2 * H_ + 4 * rq);
            float4 v0 = *reinterpret_cast<const float4*>(&n0s[rrow][4 * rq]);
            float4 u  = *reinterpret_cast<const float4*>(&n1s[rrow][4 * rq]);
            float4 g = make_float4(sigm_(s.x + bv.x) + v0.x,
                                   sigm_(s.y + bv.y) + v0.y,
                                   sigm_(s.z + bv.z) + v0.z,
                                   sigm_(s.w + bv.w) + v0.w);
            float4 hn = make_float4(0.5f * (u.x + g.x), 0.5f * (u.y + g.y),
                                    0.5f * (u.z + g.z), 0.5f * (u.w + g.w));
            *reinterpret_cast<float4*>(&hs[rrow][4 * rq]) = hn;
            if (layer == 0) {
                __stcg(reinterpret_cast<float4*>(&g_h0buf[pair][t][rrow][4 * rq]), hn);
                __threadfence();
            } else {
                *reinterpret_cast<float4*>(
                    out + ((size_t)(r0 + rrow) * T_ + t) * H_ + 4 * rq) = hn;
            }
        } else {
            bar_arrive_(BARP, NT);
            if (layer == 1 && t + 1 < T_ && tid == (((rg2 + 1) & 3) << 7)) {
                int v;
                do {
                    asm volatile("ld.acquire.gpu.global.s32 %0, [%1];"
                                 : "=r"(v) : "l"(&g_flags[pair * 32]) : "memory");
                    if (v < t + 2) __nanosleep(64);
                } while (v < t + 2);
            }
        }
        ld_grp(wa, WqWiN, 2); ld_grp(wb, WqWiN, 3);
        bar_sync_(BARA, NT);
        if (layer == 0 && tid == (rg2 << 7))
            asm volatile("st.release.gpu.global.s32 [%0], %1;"
                         :: "l"(&g_flags[pair * 32]), "r"(t + 1) : "memory");
    }

    {
        int row = tid >> 8, j = tid & 255;
        hout[((size_t)layer * B_ + r0 + row) * H_ + j] = hs[row][j];
    }
}

extern "C" void kernel_launch(void* const* d_in, const int* in_sizes, int n_in,
                              void* d_out, int out_size) {
    const float* x      = (const float*)d_in[0];
    const float* hidden = (const float*)d_in[1];
    const float* Win0   = (const float*)d_in[2];
    const float* Wh0    = (const float*)d_in[3];
    const float* b0     = (const float*)d_in[4];
    const float* Win1   = (const float*)d_in[5];
    const float* Wh1    = (const float*)d_in[6];
    const float* b1     = (const float*)d_in[7];

    float* out  = (float*)d_out;                  // [B,T,H]
    float* hout = out + (size_t)B_ * T_ * H_;     // [L,B,H]

    reset_flags_kernel<<<1, NPAIR>>>();
    rnn_rot_kernel<<<2 * NPAIR, NT>>>(x, hidden, Win0, Wh0, b0,
                                      Win1, Wh1, b1, out, hout);
}

// round 14
// speedup vs baseline: 1.3932x; 1.3932x over previous
#include <cuda_runtime.h>
#include <cstdint>

#define B_ 128
#define T_ 64
#define D_ 256
#define H_ 256
#define NT 512
#define NPAIR 64
#define HH (H_ * H_)
#define BARP 1
#define BARA 2

// R8 base (fixed reducers tid<128, all threads GEMM, producer/consumer layer
// pipeline) + carried-accumulator Wi overlap: in(t+1)@Wi(t+1) runs as stage 4
// of cell t, overlapped with the node-2 reduce; stage A of cell t+1 is then a
// single h@Wh0 pass accumulating onto the carried partial. + MUFU activations.
// R13 fix: stage 4 must refill wa/wb with Wi(t+1) rows 8-15 before its pass
// (they still held Wh2 rows 8-15).

__device__ float g_h0buf[NPAIR][T_][2][H_];
__device__ int   g_flags[NPAIR * 32];

__device__ __forceinline__ void bar_arrive_(int id, int cnt) {
    asm volatile("bar.arrive %0, %1;" :: "r"(id), "r"(cnt) : "memory");
}
__device__ __forceinline__ void bar_sync_(int id, int cnt) {
    asm volatile("bar.sync %0, %1;" :: "r"(id), "r"(cnt) : "memory");
}
__device__ __forceinline__ float tanh_(float x) {
    return __fdividef(2.f, 1.f + __expf(-2.f * x)) - 1.f;
}
__device__ __forceinline__ float sigm_(float x) {
    return __fdividef(1.f, 1.f + __expf(-x));
}
__device__ __forceinline__ void f4fma(float4& a, float s, const float4 w) {
    a.x = fmaf(s, w.x, a.x); a.y = fmaf(s, w.y, a.y);
    a.z = fmaf(s, w.z, a.z); a.w = fmaf(s, w.w, a.w);
}
__device__ __forceinline__ float4 f4add(float4 a, float4 b) {
    return make_float4(a.x + b.x, a.y + b.y, a.z + b.z, a.w + b.w);
}
__device__ __forceinline__ void ld_grp(float4 (&w)[4], const float4* __restrict__ Wq, int g) {
    #pragma unroll
    for (int k = 0; k < 4; ++k) w[k] = Wq[g * 256 + k * 64];
}
__device__ __forceinline__ void fma_grp(const float4 (&w)[4], const float4 A0,
                                        const float4 A1, float4& c0, float4& c1) {
    f4fma(c0, A0.x, w[0]); f4fma(c1, A1.x, w[0]);
    f4fma(c0, A0.y, w[1]); f4fma(c1, A1.y, w[1]);
    f4fma(c0, A0.z, w[2]); f4fma(c1, A1.z, w[2]);
    f4fma(c0, A0.w, w[3]); f4fma(c1, A1.w, w[3]);
}

// One 256-k matrix pass over this thread's 32-k slice (8 groups of 4 rows).
// Entry: wp/w1/wa/wb = W rows 0-15. Exit: wp/w1 = Wn rows 0-7.
__device__ __forceinline__ void matpass(
    const float4* __restrict__ W, const float4* __restrict__ Wn,
    const float4* __restrict__ a0, const float4* __restrict__ a1,
    float4 (&wp)[4], float4 (&w1)[4], float4 (&wa)[4], float4 (&wb)[4],
    float4& c0, float4& c1)
{
    fma_grp(wp, a0[0], a1[0], c0, c1); ld_grp(wp, Wn, 0);
    fma_grp(w1, a0[1], a1[1], c0, c1); ld_grp(w1, Wn, 1);
    fma_grp(wa, a0[2], a1[2], c0, c1); ld_grp(wa, W, 4);
    fma_grp(wb, a0[3], a1[3], c0, c1); ld_grp(wb, W, 5);
    fma_grp(wa, a0[4], a1[4], c0, c1); ld_grp(wa, W, 6);
    fma_grp(wb, a0[5], a1[5], c0, c1); ld_grp(wb, W, 7);
    fma_grp(wa, a0[6], a1[6], c0, c1);
    fma_grp(wb, a0[7], a1[7], c0, c1);
}

__device__ __forceinline__ float4 reduce8(const float4 (&p)[8][2][64], int row, int q) {
    float4 s  = f4add(p[0][row][q], p[1][row][q]);
    float4 s2 = f4add(p[2][row][q], p[3][row][q]);
    float4 s3 = f4add(p[4][row][q], p[5][row][q]);
    float4 s4 = f4add(p[6][row][q], p[7][row][q]);
    return f4add(f4add(s, s2), f4add(s3, s4));
}

__global__ void reset_flags_kernel() {
    g_flags[threadIdx.x * 32] = 0;
}

__global__ void __launch_bounds__(NT, 1)
rnn_ol_kernel(const float* __restrict__ x,       // [B,T,D]
              const float* __restrict__ hidden,  // [L,B,H]
              const float* __restrict__ Win0,    // [T,D,H]
              const float* __restrict__ Wh0,     // [T,3,H,H]
              const float* __restrict__ b0in,    // [T,3,H]
              const float* __restrict__ Win1,    // [T,H,H]
              const float* __restrict__ Wh1,     // [T,3,H,H]
              const float* __restrict__ b1in,    // [T,3,H]
              float* __restrict__ out,           // [B,T,H]
              float* __restrict__ hout)          // [L,B,H]
{
    __shared__ __align__(16) float xs[2][H_];
    __shared__ __align__(16) float hs[2][H_];
    __shared__ __align__(16) float n0s[2][H_];
    __shared__ __align__(16) float n1s[2][H_];
    __shared__ __align__(16) float bs[2][3][H_];
    __shared__ __align__(16) float4 part[8][2][64];

    const int tid = threadIdx.x;
    const int q = tid & 63;
    const int kc = tid >> 6;
    const int pair = blockIdx.x >> 1;
    const int layer = blockIdx.x & 1;
    const int r0 = pair * 2;

    const float* Wi_base   = layer ? Win1 : Win0;
    const float* Wh_base   = layer ? Wh1 : Wh0;
    const float* bias_base = layer ? b1in : b0in;

    {
        int row = tid >> 8, j = tid & 255;
        hs[row][j] = hidden[((size_t)layer * B_ + r0 + row) * H_ + j];
        if (layer == 0)
            xs[row][j] = x[((size_t)(r0 + row) * T_) * D_ + j];
    }
    if (tid < 192)
        *reinterpret_cast<float4*>(&bs[0][0][0] + tid * 4) =
            *reinterpret_cast<const float4*>(bias_base + tid * 4);
    if (layer == 1 && tid == 0) {        // need h0(0) before the bootstrap pass
        int v;
        do {
            asm volatile("ld.acquire.gpu.global.s32 %0, [%1];"
                         : "=r"(v) : "l"(&g_flags[pair * 32]) : "memory");
            if (v < 1) __nanosleep(64);
        } while (v < 1);
    }
    __syncthreads();

    const int woff = kc * 32 * 64 + q;           // float4 units
    const float4* hs0 = reinterpret_cast<const float4*>(hs[0]) + kc * 8;
    const float4* hs1 = reinterpret_cast<const float4*>(hs[1]) + kc * 8;
    const float4* xs0 = reinterpret_cast<const float4*>(xs[0]) + kc * 8;
    const float4* xs1 = reinterpret_cast<const float4*>(xs[1]) + kc * 8;
    const float4* n00 = reinterpret_cast<const float4*>(n0s[0]) + kc * 8;
    const float4* n01 = reinterpret_cast<const float4*>(n0s[1]) + kc * 8;
    const float4* n10 = reinterpret_cast<const float4*>(n1s[0]) + kc * 8;
    const float4* n11 = reinterpret_cast<const float4*>(n1s[1]) + kc * 8;

    float4 wp[4], w1[4], wa[4], wb[4];
    float4 acc0, acc1;                    // carried: in(t)@Wi(t) at cell entry
    float4 v0 = {0,0,0,0}, u = {0,0,0,0}; // reducer-persistent (tid<128)

    // ---- bootstrap: acc = in(0)@Wi(0); exit bufs = Wh0(0) rows 0-15 ----
    {
        const float4* WqWi0 = reinterpret_cast<const float4*>(Wi_base) + woff;
        const float4* WqWh00 = reinterpret_cast<const float4*>(Wh_base) + woff;
        ld_grp(wp, WqWi0, 0); ld_grp(w1, WqWi0, 1);
        ld_grp(wa, WqWi0, 2); ld_grp(wb, WqWi0, 3);
        const float4* i0 = (layer == 0) ? xs0
            : reinterpret_cast<const float4*>(&g_h0buf[pair][0][0][0]) + kc * 8;
        const float4* i1 = (layer == 0) ? xs1
            : reinterpret_cast<const float4*>(&g_h0buf[pair][0][1][0]) + kc * 8;
        acc0 = make_float4(0.f,0.f,0.f,0.f); acc1 = acc0;
        matpass(WqWi0, WqWh00, i0, i1, wp, w1, wa, wb, acc0, acc1);
        ld_grp(wa, WqWh00, 2); ld_grp(wb, WqWh00, 3);
    }

    for (int t = 0; t < T_; ++t) {
        const float* WhT = Wh_base + (size_t)t * 3 * HH;
        const float4* WqWh0 = reinterpret_cast<const float4*>(WhT) + woff;
        const float4* WqWh1 = WqWh0 + HH / 4;
        const float4* WqWh2 = WqWh0 + 2 * (HH / 4);
        const int tn = (t + 1 < T_) ? t + 1 : 0;
        const float4* WqWiN = reinterpret_cast<const float4*>(
            Wi_base + (size_t)tn * (D_ * H_)) + woff;
        const float4* WqWh0N = reinterpret_cast<const float4*>(
            Wh_base + (size_t)tn * 3 * HH) + woff;
        const float* bsc = &bs[t & 1][0][0];
        const float4* bnext =
            reinterpret_cast<const float4*>(bias_base + (size_t)tn * 3 * H_);

        // ============ stage 1: acc += h@Wh0 ; reduce0 = tanh ============
        matpass(WqWh0, WqWh1, hs0, hs1, wp, w1, wa, wb, acc0, acc1);
        part[kc][0][q] = acc0; part[kc][1][q] = acc1;
        if (tid < 128) {
            bar_sync_(BARP, NT);
            float4 s = reduce8(part, tid >> 6, q);
            float4 bv = *reinterpret_cast<const float4*>(bsc + 4 * q);
            v0 = make_float4(tanh_(s.x + bv.x), tanh_(s.y + bv.y),
                             tanh_(s.z + bv.z), tanh_(s.w + bv.w));
            *reinterpret_cast<float4*>(&n0s[tid >> 6][4 * q]) = v0;
        } else {
            bar_arrive_(BARP, NT);
            if (tid < 320)                          // bias(t+1)
                reinterpret_cast<float4*>(&bs[(t + 1) & 1][0][0])[tid - 128] =
                    bnext[tid - 128];
        }
        ld_grp(wa, WqWh1, 2); ld_grp(wb, WqWh1, 3);
        bar_sync_(BARA, NT);

        // ============ stage 2: n0@Wh1 ; reduce1 = relu + n0 ============
        acc0 = make_float4(0.f,0.f,0.f,0.f); acc1 = acc0;
        matpass(WqWh1, WqWh2, n00, n01, wp, w1, wa, wb, acc0, acc1);
        part[kc][0][q] = acc0; part[kc][1][q] = acc1;
        if (tid < 128) {
            bar_sync_(BARP, NT);
            float4 s = reduce8(part, tid >> 6, q);
            float4 bv = *reinterpret_cast<const float4*>(bsc + H_ + 4 * q);
            u = make_float4(fmaxf(s.x + bv.x, 0.f) + v0.x,
                            fmaxf(s.y + bv.y, 0.f) + v0.y,
                            fmaxf(s.z + bv.z, 0.f) + v0.z,
                            fmaxf(s.w + bv.w, 0.f) + v0.w);
            *reinterpret_cast<float4*>(&n1s[tid >> 6][4 * q]) = u;
        } else {
            bar_arrive_(BARP, NT);
            if (layer == 0 && t + 1 < T_ && tid >= 384) {   // x(t+1) prefetch
                int i = tid - 384;
                int rr = i >> 6, col = (i & 63) * 4;
                *reinterpret_cast<float4*>(&xs[rr][col]) =
                    *reinterpret_cast<const float4*>(
                        &x[((size_t)(r0 + rr) * T_ + t + 1) * D_ + col]);
            }
            if (layer == 1 && t + 1 < T_ && tid == 352) {   // h0(t+1) flag
                int v;
                do {
                    asm volatile("ld.acquire.gpu.global.s32 %0, [%1];"
                                 : "=r"(v) : "l"(&g_flags[pair * 32]) : "memory");
                    if (v < t + 2) __nanosleep(64);
                } while (v < t + 2);
            }
        }
        ld_grp(wa, WqWh2, 2); ld_grp(wb, WqWh2, 3);
        bar_sync_(BARA, NT);

        // ==== stage 3: n1@Wh2 ; reduce2 overlapped with stage 4 (Wi(t+1)) ====
        acc0 = make_float4(0.f,0.f,0.f,0.f); acc1 = acc0;
        matpass(WqWh2, WqWiN, n10, n11, wp, w1, wa, wb, acc0, acc1);
        part[kc][0][q] = acc0; part[kc][1][q] = acc1;
        if (tid < 128) {
            bar_sync_(BARP, NT);
            float4 s = reduce8(part, tid >> 6, q);
            float4 bv = *reinterpret_cast<const float4*>(bsc + 2 * H_ + 4 * q);
            float4 g = make_float4(sigm_(s.x + bv.x) + v0.x,
                                   sigm_(s.y + bv.y) + v0.y,
                                   sigm_(s.z + bv.z) + v0.z,
                                   sigm_(s.w + bv.w) + v0.w);
            float4 hn = make_float4(0.5f * (u.x + g.x), 0.5f * (u.y + g.y),
                                    0.5f * (u.z + g.z), 0.5f * (u.w + g.w));
            *reinterpret_cast<float4*>(&hs[tid >> 6][4 * q]) = hn;
            if (layer == 0) {
                __stcg(reinterpret_cast<float4*>(&g_h0buf[pair][t][tid >> 6][4 * q]), hn);
                __threadfence();
            } else {
                *reinterpret_cast<float4*>(
                    out + ((size_t)(r0 + (tid >> 6)) * T_ + t) * H_ + 4 * q) = hn;
            }
        } else {
            bar_arrive_(BARP, NT);
        }
        // stage 4: acc = in(t+1)@Wi(t+1)  (hidden under reduce2 for tid>=128)
        if (t + 1 < T_) {
            const float4* iN0 = (layer == 0) ? xs0
                : reinterpret_cast<const float4*>(&g_h0buf[pair][t + 1][0][0]) + kc * 8;
            const float4* iN1 = (layer == 0) ? xs1
                : reinterpret_cast<const float4*>(&g_h0buf[pair][t + 1][1][0]) + kc * 8;
            ld_grp(wa, WqWiN, 2); ld_grp(wb, WqWiN, 3);   // R13 FIX: Wi rows 8-15
            acc0 = make_float4(0.f,0.f,0.f,0.f); acc1 = acc0;
            matpass(WqWiN, WqWh0N, iN0, iN1, wp, w1, wa, wb, acc0, acc1);
            ld_grp(wa, WqWh0N, 2); ld_grp(wb, WqWh0N, 3);
        }
        bar_sync_(BARA, NT);
        if (layer == 0 && tid == 0)
            asm volatile("st.release.gpu.global.s32 [%0], %1;"
                         :: "l"(&g_flags[pair * 32]), "r"(t + 1) : "memory");
    }

    {
        int row = tid >> 8, j = tid & 255;
        hout[((size_t)layer * B_ + r0 + row) * H_ + j] = hs[row][j];
    }
}

extern "C" void kernel_launch(void* const* d_in, const int* in_sizes, int n_in,
                              void* d_out, int out_size) {
    const float* x      = (const float*)d_in[0];
    const float* hidden = (const float*)d_in[1];
    const float* Win0   = (const float*)d_in[2];
    const float* Wh0    = (const float*)d_in[3];
    const float* b0     = (const float*)d_in[4];
    const float* Win1   = (const float*)d_in[5];
    const float* Wh1    = (const float*)d_in[6];
    const float* b1     = (const float*)d_in[7];

    float* out  = (float*)d_out;                  // [B,T,H]
    float* hout = out + (size_t)B_ * T_ * H_;     // [L,B,H]

    reset_flags_kernel<<<1, NPAIR>>>();
    rnn_ol_kernel<<<2 * NPAIR, NT>>>(x, hidden, Win0, Wh0, b0,
                                     Win1, Wh1, b1, out, hout);
}